// round 1
// baseline (speedup 1.0000x reference)
#include <cuda_runtime.h>
#include <math.h>

#define NROWS 262144
#define NBLK  8
#define BS    16

// Unified per-block 16x16 matrices: y[o] = sum_d x[d] * M[j][d][o]
// Stored as float4 quads: g_M4[j*64 + d*4 + q] = M[j][d][4q..4q+3]
__device__ float4 g_M4[NBLK * BS * 4];

// Build the unified block matrices from the three parameter families.
// DENSE blocks {0,3,6} <- W_dense[k][o][d] (y = x @ W^T)
// DIAG  blocks {1,4,7} <- diag(s)
// LR    blocks {2,5}   <- (V U^T)[d][o] = sum_r V[d][r] U[o][r]
__global__ void bdla_prep(const float* __restrict__ W,
                          const float* __restrict__ s,
                          const float* __restrict__ U,
                          const float* __restrict__ V) {
    float* gm = (float*)g_M4;
    for (int e = threadIdx.x + blockIdx.x * blockDim.x; e < NBLK * BS * BS;
         e += blockDim.x * gridDim.x) {
        int j = e >> 8;            // block id 0..7
        int rem = e & 255;
        int d = rem >> 4;          // input index in block
        int o = rem & 15;          // output index in block
        float val;
        if (j == 0 || j == 3 || j == 6) {
            int k = j / 3;
            val = W[k * 256 + o * 16 + d];
        } else if (j == 1 || j == 4 || j == 7) {
            int k = (j - 1) / 3;
            val = (d == o) ? s[k * 16 + d] : 0.0f;
        } else { // j == 2 || j == 5
            int k = (j - 2) / 3;
            float acc = 0.0f;
            #pragma unroll
            for (int r = 0; r < 4; ++r)
                acc += V[k * 64 + d * 4 + r] * U[k * 64 + o * 4 + r];
            val = acc;
        }
        gm[j * 256 + d * 16 + o] = val;
    }
}

// One warp per row. Lane t: block j = t>>2, output quad q = t&3.
// Weights for this lane's 4 outputs (16 inputs x 4 outputs) live in registers.
__global__ void __launch_bounds__(256)
bdla_main(const float* __restrict__ x, float* __restrict__ y) {
    const int lane  = threadIdx.x & 31;
    const int gwarp = (blockIdx.x * blockDim.x + threadIdx.x) >> 5;
    const int nwarp = (gridDim.x * blockDim.x) >> 5;
    const int q = lane & 3;

    // Load this lane's 64 weights into registers (hits L1/L2; amortized
    // over ~16 rows per warp).
    float4 w[16];
    {
        const float4* Mp = g_M4 + ((lane >> 2) << 6) + q;
        #pragma unroll
        for (int d = 0; d < 16; ++d) w[d] = Mp[d * 4];
    }

    const float4* __restrict__ xin  = (const float4*)x;
    float4* __restrict__       yout = (float4*)y;

    for (int r = gwarp; r < NROWS; r += 2 * nwarp) {
        const int r2 = r + nwarp;
        // Front-batch both loads for MLP.
        float4 xa = xin[(size_t)r * 32 + lane];
        float4 xb;
        const bool has2 = (r2 < NROWS);
        if (has2) xb = xin[(size_t)r2 * 32 + lane];

        #pragma unroll
        for (int pass = 0; pass < 2; ++pass) {
            if (pass == 1 && !has2) break;
            const float4 xv = (pass == 0) ? xa : xb;
            const int    rr = (pass == 0) ? r  : r2;

            float y0 = 0.f, y1 = 0.f, y2 = 0.f, y3 = 0.f;
            #pragma unroll
            for (int sblk = 0; sblk < 4; ++sblk) {
                const int src = (lane & 28) + sblk;  // lane 4j+s of my block
                const float a0 = __shfl_sync(0xffffffffu, xv.x, src);
                const float a1 = __shfl_sync(0xffffffffu, xv.y, src);
                const float a2 = __shfl_sync(0xffffffffu, xv.z, src);
                const float a3 = __shfl_sync(0xffffffffu, xv.w, src);
                const float4 w0 = w[4 * sblk + 0];
                const float4 w1 = w[4 * sblk + 1];
                const float4 w2 = w[4 * sblk + 2];
                const float4 w3 = w[4 * sblk + 3];
                y0 = fmaf(a0, w0.x, y0); y1 = fmaf(a0, w0.y, y1);
                y2 = fmaf(a0, w0.z, y2); y3 = fmaf(a0, w0.w, y3);
                y0 = fmaf(a1, w1.x, y0); y1 = fmaf(a1, w1.y, y1);
                y2 = fmaf(a1, w1.z, y2); y3 = fmaf(a1, w1.w, y3);
                y0 = fmaf(a2, w2.x, y0); y1 = fmaf(a2, w2.y, y1);
                y2 = fmaf(a2, w2.z, y2); y3 = fmaf(a2, w2.w, y3);
                y0 = fmaf(a3, w3.x, y0); y1 = fmaf(a3, w3.y, y1);
                y2 = fmaf(a3, w3.z, y2); y3 = fmaf(a3, w3.w, y3);
            }

            // L2 norm over the full 128-wide row (all 32 lanes).
            float ss = y0 * y0 + y1 * y1 + y2 * y2 + y3 * y3;
            #pragma unroll
            for (int m = 16; m >= 1; m >>= 1)
                ss += __shfl_xor_sync(0xffffffffu, ss, m);
            const float inv = __fdividef(1.0f, sqrtf(ss) + 1e-8f);

            yout[(size_t)rr * 32 + lane] =
                make_float4(y0 * inv, y1 * inv, y2 * inv, y3 * inv);
        }
    }
}

extern "C" void kernel_launch(void* const* d_in, const int* in_sizes, int n_in,
                              void* d_out, int out_size) {
    const float* x = (const float*)d_in[0];
    const float* W = (const float*)d_in[1];
    const float* s = (const float*)d_in[2];
    const float* U = (const float*)d_in[3];
    const float* V = (const float*)d_in[4];
    float* out = (float*)d_out;

    bdla_prep<<<8, 256>>>(W, s, U, V);
    // 2048 CTAs x 8 warps = 16384 warps; 16 rows/warp, unroll-2 -> 8 iters.
    bdla_main<<<2048, 256>>>(x, out);
}